// round 5
// baseline (speedup 1.0000x reference)
#include <cuda_runtime.h>
#include <cstdint>

// Problem shape (fixed by reference)
constexpr int EMBED = 256;
constexpr int BATCH = 64;
constexpr int BLOCK = 2048;
constexpr int NTOK  = BATCH * BLOCK;       // 131072 tokens
constexpr int VEC_PER_ROW = EMBED / 4;     // 64 float4 per row

__device__ __forceinline__ void stwt_f4(float4* p, float4 v) {
    // write-through, no-write-allocate: output is never re-read, so keep the
    // 256MB/launch of writes from occupying L2 lines. This leaves (nearly)
    // the whole 126MB L2 for the 128MB embedding table, collapsing gather
    // misses in graph-replay steady state.
    asm volatile("st.global.wt.v4.f32 [%0], {%1,%2,%3,%4};"
                 :: "l"(p), "f"(v.x), "f"(v.y), "f"(v.z), "f"(v.w) : "memory");
}

__global__ __launch_bounds__(256)
void embed_softmax_kernel(const int* __restrict__ idx,
                          const float* __restrict__ emb,
                          float* __restrict__ out) {
    const int warp = (blockIdx.x * blockDim.x + threadIdx.x) >> 5;
    const int lane = threadIdx.x & 31;
    if (warp >= NTOK) return;

    const int row = __ldg(idx + warp);
    const float4* __restrict__ src =
        reinterpret_cast<const float4*>(emb + (size_t)row * EMBED);

    // 64 float4 per row, 32 lanes -> 2 vec loads per lane (fully coalesced 1KB)
    float4 a = __ldg(src + lane);
    float4 b = __ldg(src + 32 + lane);

    float4* __restrict__ logit_dst =
        reinterpret_cast<float4*>(out) + (size_t)warp * VEC_PER_ROW;
    float4* __restrict__ prob_dst =
        logit_dst + (size_t)NTOK * VEC_PER_ROW;

    // logits: straight copy of gathered row
    stwt_f4(logit_dst + lane,      a);
    stwt_f4(logit_dst + 32 + lane, b);

    float e0 = __expf(a.x), e1 = __expf(a.y), e2 = __expf(a.z), e3 = __expf(a.w);
    float e4 = __expf(b.x), e5 = __expf(b.y), e6 = __expf(b.z), e7 = __expf(b.w);

    float s = ((e0 + e1) + (e2 + e3)) + ((e4 + e5) + (e6 + e7));
    #pragma unroll
    for (int o = 16; o > 0; o >>= 1)
        s += __shfl_xor_sync(0xFFFFFFFFu, s, o);

    const float inv = __frcp_rn(s);

    stwt_f4(prob_dst + lane,      make_float4(e0 * inv, e1 * inv, e2 * inv, e3 * inv));
    stwt_f4(prob_dst + 32 + lane, make_float4(e4 * inv, e5 * inv, e6 * inv, e7 * inv));
}

extern "C" void kernel_launch(void* const* d_in, const int* in_sizes, int n_in,
                              void* d_out, int out_size) {
    const int* idx;
    const float* emb;
    if (in_sizes[0] == NTOK) {
        idx = (const int*)d_in[0];
        emb = (const float*)d_in[1];
    } else {
        idx = (const int*)d_in[1];
        emb = (const float*)d_in[0];
    }
    float* out = (float*)d_out;

    // one warp per token: 131072 warps -> 256-thread blocks, 8 warps each
    const int threads = 256;
    const int blocks = (NTOK * 32) / threads;  // 16384
    embed_softmax_kernel<<<blocks, threads>>>(idx, emb, out);
}

// round 6
// speedup vs baseline: 1.0103x; 1.0103x over previous
#include <cuda_runtime.h>
#include <cstdint>

// Problem shape (fixed by reference)
constexpr int EMBED = 256;
constexpr int BATCH = 64;
constexpr int BLOCK = 2048;
constexpr int NTOK  = BATCH * BLOCK;       // 131072 tokens
constexpr int VEC_PER_ROW = EMBED / 4;     // 64 float4 per row

// Policy-matrix experiment: default write-back/write-allocate stores.
// Measured so far: .cs 55.6us, .wt 57.8us, with identical DRAM traffic and
// identical read-miss volume -> the eviction hints are not protecting the
// table. Default write-back lets L2 batch the 256MB store stream and drain
// dirty lines in large bursts, which should schedule better against the
// random read stream at the HBM controllers.

__global__ __launch_bounds__(256)
void embed_softmax_kernel(const int* __restrict__ idx,
                          const float* __restrict__ emb,
                          float* __restrict__ out) {
    const int warp = (blockIdx.x * blockDim.x + threadIdx.x) >> 5;
    const int lane = threadIdx.x & 31;
    if (warp >= NTOK) return;

    const int row = __ldg(idx + warp);
    const float4* __restrict__ src =
        reinterpret_cast<const float4*>(emb + (size_t)row * EMBED);

    // 64 float4 per row, 32 lanes -> 2 vec loads per lane (fully coalesced 1KB)
    float4 a = __ldg(src + lane);
    float4 b = __ldg(src + 32 + lane);

    float4* __restrict__ logit_dst =
        reinterpret_cast<float4*>(out) + (size_t)warp * VEC_PER_ROW;
    float4* __restrict__ prob_dst =
        logit_dst + (size_t)NTOK * VEC_PER_ROW;

    // logits: straight copy of gathered row (default store policy)
    logit_dst[lane]      = a;
    logit_dst[32 + lane] = b;

    float e0 = __expf(a.x), e1 = __expf(a.y), e2 = __expf(a.z), e3 = __expf(a.w);
    float e4 = __expf(b.x), e5 = __expf(b.y), e6 = __expf(b.z), e7 = __expf(b.w);

    float s = ((e0 + e1) + (e2 + e3)) + ((e4 + e5) + (e6 + e7));
    #pragma unroll
    for (int o = 16; o > 0; o >>= 1)
        s += __shfl_xor_sync(0xFFFFFFFFu, s, o);

    const float inv = __frcp_rn(s);

    prob_dst[lane]      = make_float4(e0 * inv, e1 * inv, e2 * inv, e3 * inv);
    prob_dst[32 + lane] = make_float4(e4 * inv, e5 * inv, e6 * inv, e7 * inv);
}

extern "C" void kernel_launch(void* const* d_in, const int* in_sizes, int n_in,
                              void* d_out, int out_size) {
    const int* idx;
    const float* emb;
    if (in_sizes[0] == NTOK) {
        idx = (const int*)d_in[0];
        emb = (const float*)d_in[1];
    } else {
        idx = (const int*)d_in[1];
        emb = (const float*)d_in[0];
    }
    float* out = (float*)d_out;

    // one warp per token: 131072 warps -> 256-thread blocks, 8 warps each
    const int threads = 256;
    const int blocks = (NTOK * 32) / threads;  // 16384
    embed_softmax_kernel<<<blocks, threads>>>(idx, emb, out);
}

// round 7
// speedup vs baseline: 1.0295x; 1.0190x over previous
#include <cuda_runtime.h>
#include <cstdint>

// Problem shape (fixed by reference)
constexpr int EMBED = 256;
constexpr int BATCH = 64;
constexpr int BLOCK = 2048;
constexpr int NTOK  = BATCH * BLOCK;       // 131072 tokens
constexpr int VEC_PER_ROW = EMBED / 4;     // 64 float4 per row

// Deterministic L2 partition: rows < CUTOFF are loaded evict_last (pinned
// resident after warmup, 112MB of the 126MB L2), rows >= CUTOFF are loaded
// evict_first (transient, 12.5% of lookups, never displace the pinned set).
// This replaces LRU-thrash over a 128MB working set with a frozen 112MB
// cache + small streaming remainder.
constexpr int CUTOFF_ROW = 112000;

__device__ __forceinline__ void stcs_f4(float4* p, float4 v) {
    // streaming store: evict-first so output writes churn in the small
    // non-pinned pool instead of evicting the pinned table subset
    asm volatile("st.global.cs.v4.f32 [%0], {%1,%2,%3,%4};"
                 :: "l"(p), "f"(v.x), "f"(v.y), "f"(v.z), "f"(v.w) : "memory");
}

struct f8 { float v[8]; };

__device__ __forceinline__ f8 ldg_last_f8(const float* p) {
    f8 r;
    asm volatile("ld.global.nc.L2::evict_last.v8.f32 "
                 "{%0,%1,%2,%3,%4,%5,%6,%7}, [%8];"
                 : "=f"(r.v[0]), "=f"(r.v[1]), "=f"(r.v[2]), "=f"(r.v[3]),
                   "=f"(r.v[4]), "=f"(r.v[5]), "=f"(r.v[6]), "=f"(r.v[7])
                 : "l"(p));
    return r;
}

__device__ __forceinline__ f8 ldg_first_f8(const float* p) {
    f8 r;
    asm volatile("ld.global.nc.L2::evict_first.v8.f32 "
                 "{%0,%1,%2,%3,%4,%5,%6,%7}, [%8];"
                 : "=f"(r.v[0]), "=f"(r.v[1]), "=f"(r.v[2]), "=f"(r.v[3]),
                   "=f"(r.v[4]), "=f"(r.v[5]), "=f"(r.v[6]), "=f"(r.v[7])
                 : "l"(p));
    return r;
}

__global__ __launch_bounds__(256)
void embed_softmax_kernel(const int* __restrict__ idx,
                          const float* __restrict__ emb,
                          float* __restrict__ out) {
    const int warp = (blockIdx.x * blockDim.x + threadIdx.x) >> 5;
    const int lane = threadIdx.x & 31;
    if (warp >= NTOK) return;

    const int row = __ldg(idx + warp);
    const float* src = emb + (size_t)row * EMBED + lane * 8;

    // warp-uniform branch: all lanes share the same row
    f8 a;
    if (row < CUTOFF_ROW) {
        a = ldg_last_f8(src);    // pinned partition
    } else {
        a = ldg_first_f8(src);   // transient partition
    }

    float4* __restrict__ logit_dst =
        reinterpret_cast<float4*>(out) + (size_t)warp * VEC_PER_ROW;
    float4* __restrict__ prob_dst =
        logit_dst + (size_t)NTOK * VEC_PER_ROW;

    // logits: straight copy of the gathered row.
    // lane's 8 floats are contiguous: two adjacent float4 at vec index lane*2.
    stcs_f4(logit_dst + lane * 2,
            make_float4(a.v[0], a.v[1], a.v[2], a.v[3]));
    stcs_f4(logit_dst + lane * 2 + 1,
            make_float4(a.v[4], a.v[5], a.v[6], a.v[7]));

    float e[8];
    #pragma unroll
    for (int i = 0; i < 8; i++) e[i] = __expf(a.v[i]);

    float s = ((e[0] + e[1]) + (e[2] + e[3])) + ((e[4] + e[5]) + (e[6] + e[7]));
    #pragma unroll
    for (int o = 16; o > 0; o >>= 1)
        s += __shfl_xor_sync(0xFFFFFFFFu, s, o);

    const float inv = __frcp_rn(s);

    stcs_f4(prob_dst + lane * 2,
            make_float4(e[0] * inv, e[1] * inv, e[2] * inv, e[3] * inv));
    stcs_f4(prob_dst + lane * 2 + 1,
            make_float4(e[4] * inv, e[5] * inv, e[6] * inv, e[7] * inv));
}

extern "C" void kernel_launch(void* const* d_in, const int* in_sizes, int n_in,
                              void* d_out, int out_size) {
    const int* idx;
    const float* emb;
    if (in_sizes[0] == NTOK) {
        idx = (const int*)d_in[0];
        emb = (const float*)d_in[1];
    } else {
        idx = (const int*)d_in[1];
        emb = (const float*)d_in[0];
    }
    float* out = (float*)d_out;

    // one warp per token: 131072 warps -> 256-thread blocks, 8 warps each
    const int threads = 256;
    const int blocks = (NTOK * 32) / threads;  // 16384
    embed_softmax_kernel<<<blocks, threads>>>(idx, emb, out);
}

// round 8
// speedup vs baseline: 1.0394x; 1.0096x over previous
#include <cuda_runtime.h>
#include <cstdint>

// Problem shape (fixed by reference)
constexpr int EMBED = 256;
constexpr int BATCH = 64;
constexpr int BLOCK = 2048;
constexpr int NTOK  = BATCH * BLOCK;       // 131072 tokens
constexpr int VEC_PER_ROW = EMBED / 4;     // 64 float4 per row

// Config locked from the measured policy matrix (6 variants):
//   .cs v4 stores + plain __ldg v4 loads + 1 token/warp = 55.6us (best).
// All cache-hint / MLP / width variants were neutral-to-worse with identical
// DRAM traffic (~310MB) -> kernel is at the HBM mixed read/write floor.
// This round's single variable: store logits right after the loads so the
// write stream starts early and overlaps the exp/reduce chain.

__device__ __forceinline__ void stcs_f4(float4* p, float4 v) {
    asm volatile("st.global.cs.v4.f32 [%0], {%1,%2,%3,%4};"
                 :: "l"(p), "f"(v.x), "f"(v.y), "f"(v.z), "f"(v.w) : "memory");
}

__global__ __launch_bounds__(256)
void embed_softmax_kernel(const int* __restrict__ idx,
                          const float* __restrict__ emb,
                          float* __restrict__ out) {
    const int warp = (blockIdx.x * blockDim.x + threadIdx.x) >> 5;
    const int lane = threadIdx.x & 31;
    if (warp >= NTOK) return;

    const int row = __ldg(idx + warp);
    const float4* __restrict__ src =
        reinterpret_cast<const float4*>(emb + (size_t)row * EMBED);

    // 64 float4 per row, 32 lanes -> 2 vec loads per lane (fully coalesced 1KB)
    float4 a = __ldg(src + lane);
    float4 b = __ldg(src + 32 + lane);

    float4* __restrict__ logit_dst =
        reinterpret_cast<float4*>(out) + (size_t)warp * VEC_PER_ROW;
    float4* __restrict__ prob_dst =
        logit_dst + (size_t)NTOK * VEC_PER_ROW;

    // start the write stream immediately: logits are a straight copy
    stcs_f4(logit_dst + lane,      a);
    stcs_f4(logit_dst + 32 + lane, b);

    float e0 = __expf(a.x), e1 = __expf(a.y), e2 = __expf(a.z), e3 = __expf(a.w);
    float e4 = __expf(b.x), e5 = __expf(b.y), e6 = __expf(b.z), e7 = __expf(b.w);

    float s = ((e0 + e1) + (e2 + e3)) + ((e4 + e5) + (e6 + e7));
    #pragma unroll
    for (int o = 16; o > 0; o >>= 1)
        s += __shfl_xor_sync(0xFFFFFFFFu, s, o);

    const float inv = __frcp_rn(s);

    stcs_f4(prob_dst + lane,      make_float4(e0 * inv, e1 * inv, e2 * inv, e3 * inv));
    stcs_f4(prob_dst + 32 + lane, make_float4(e4 * inv, e5 * inv, e6 * inv, e7 * inv));
}

extern "C" void kernel_launch(void* const* d_in, const int* in_sizes, int n_in,
                              void* d_out, int out_size) {
    const int* idx;
    const float* emb;
    if (in_sizes[0] == NTOK) {
        idx = (const int*)d_in[0];
        emb = (const float*)d_in[1];
    } else {
        idx = (const int*)d_in[1];
        emb = (const float*)d_in[0];
    }
    float* out = (float*)d_out;

    // one warp per token: 131072 warps -> 256-thread blocks, 8 warps each
    const int threads = 256;
    const int blocks = (NTOK * 32) / threads;  // 16384
    embed_softmax_kernel<<<blocks, threads>>>(idx, emb, out);
}